// round 17
// baseline (speedup 1.0000x reference)
#include <cuda_runtime.h>
#include <cuda_bf16.h>
#include <mma.h>
#include <cstdint>

using namespace nvcuda;

#define NN   50000
#define DD   128
#define EE   400000
#define NMOL 256
#define OUTC 32

typedef unsigned long long u64;

// ---------------- device scratch (no allocations allowed) ----------------
__device__ float g_s1[NN * DD];
__device__ float g_s2[NN * DD];
__device__ float g_Abuf[NN * DD];
__device__ float g_mol[NMOL * DD];
__device__ int   g_is64;
// pre-split bf16 weights (hi/lo), all 3 steps
__device__ __nv_bfloat16 g_whh[3 * 64 * 64];
__device__ __nv_bfloat16 g_whl[3 * 64 * 64];
__device__ __nv_bfloat16 g_woh[3 * 64 * 128];
__device__ __nv_bfloat16 g_wol[3 * 64 * 128];

// ---------------- f32x2 helpers (precompute kernel) ----------------
__device__ __forceinline__ void fma2(u64 &d, u64 a, u64 b) {
    asm("fma.rn.f32x2 %0, %1, %2, %0;" : "+l"(d) : "l"(a), "l"(b));
}
__device__ __forceinline__ float sum2(u64 v) {
    float lo, hi;
    asm("mov.b64 {%0,%1}, %2;" : "=f"(lo), "=f"(hi) : "l"(v));
    return lo + hi;
}

// ---------------- bf16 split helpers ----------------
__device__ __forceinline__ uint32_t pack_bf16(float lo, float hi) {
    uint32_t r;
    asm("cvt.rn.bf16x2.f32 %0, %1, %2;" : "=r"(r) : "f"(hi), "f"(lo));
    return r;
}
__device__ __forceinline__ float bf_lo(uint32_t p) { return __uint_as_float(p << 16); }
__device__ __forceinline__ float bf_hi(uint32_t p) { return __uint_as_float(p & 0xFFFF0000u); }
__device__ __forceinline__ void split2(float a, float b, uint32_t &h, uint32_t &l) {
    h = pack_bf16(a, b);
    l = pack_bf16(a - bf_lo(h), b - bf_hi(h));
}

// ---------------- index width detection (int32 vs int64) ----------------
__global__ void detect_kernel(const int* p) {
    if (threadIdx.x == 0) {
        int all0 = 1;
        for (int i = 0; i < 64; i++)
            if (p[2 * i + 1] != 0) { all0 = 0; break; }
        g_is64 = all0;
    }
}
__device__ __forceinline__ int load_idx(const void* p, int i) {
    if (g_is64) return (int)((const long long*)p)[i];
    return ((const int*)p)[i];
}

// ---------------- zero fill ----------------
__global__ void zero_kernel(float4* p, int n4) {
    int i = blockIdx.x * blockDim.x + threadIdx.x;
    int stride = gridDim.x * blockDim.x;
    float4 z = make_float4(0.f, 0.f, 0.f, 0.f);
    for (; i < n4; i += stride) p[i] = z;
}

// ---------------- weight pre-split: all 3 steps, one launch ----------------
__global__ void split_w_kernel(const float* __restrict__ Wh, const float* __restrict__ Wo) {
    int i = blockIdx.x * blockDim.x + threadIdx.x;
    if (i < 3 * 64 * 32) {                 // Wh pairs
        int idx = i * 2;
        uint32_t h, l;
        split2(Wh[idx], Wh[idx + 1], h, l);
        *(uint32_t*)&g_whh[idx] = h;
        *(uint32_t*)&g_whl[idx] = l;
    } else {
        int j = i - 3 * 64 * 32;
        if (j < 3 * 64 * 64) {             // Wo pairs
            int idx = j * 2;
            uint32_t h, l;
            split2(Wo[idx], Wo[idx + 1], h, l);
            *(uint32_t*)&g_woh[idx] = h;
            *(uint32_t*)&g_wol[idx] = l;
        }
    }
}

// ================= precompute: A = S @ [Win_top | Win_bot] (f32x2, proven) ===========
#define PC_STRIDE 132
#define PC_SMEM_BYTES ((128 * PC_STRIDE + 64 * PC_STRIDE) * 4)

__global__ __launch_bounds__(256, 2)
void precompute_kernel(const float* __restrict__ s, float* __restrict__ out,
                       const float* __restrict__ Win_t) {
    extern __shared__ float sm[];
    float* wT = sm;
    float* ss = sm + 128 * PC_STRIDE;
    int tid = threadIdx.x;
    int abase = blockIdx.x * 64;

    for (int i = tid; i < 128 * 128; i += 256) {
        int k = i >> 7, j = i & 127;
        float v = (j < 64) ? Win_t[k * 64 + j] : Win_t[(128 + k) * 64 + (j - 64)];
        wT[j * PC_STRIDE + k] = v;
    }
    for (int i = tid; i < 64 * 32; i += 256) {
        int a = i >> 5, kq = (i & 31) * 4;
        int atom = abase + a;
        float4 v = (atom < NN) ? *(const float4*)&s[(size_t)atom * DD + kq]
                               : make_float4(0.f, 0.f, 0.f, 0.f);
        *(float4*)&ss[a * PC_STRIDE + kq] = v;
    }
    __syncthreads();

    int jg = tid & 31;
    int a0 = (tid >> 5) * 8;
    u64 acc[8][4];
#pragma unroll
    for (int i = 0; i < 8; i++)
#pragma unroll
        for (int c = 0; c < 4; c++) acc[i][c] = 0ull;

#pragma unroll 2
    for (int k = 0; k < 128; k += 4) {
        ulonglong2 wp[4];
#pragma unroll
        for (int c = 0; c < 4; c++)
            wp[c] = *(const ulonglong2*)&wT[(jg + 32 * c) * PC_STRIDE + k];
#pragma unroll
        for (int h = 0; h < 2; h++) {
#pragma unroll
            for (int i = 0; i < 4; i++) {
                int r = h * 4 + i;
                ulonglong2 hv = *(const ulonglong2*)&ss[(a0 + r) * PC_STRIDE + k];
#pragma unroll
                for (int c = 0; c < 4; c++) {
                    fma2(acc[r][c], hv.x, wp[c].x);
                    fma2(acc[r][c], hv.y, wp[c].y);
                }
            }
        }
    }

#pragma unroll
    for (int i = 0; i < 8; i++) {
        int atom = abase + a0 + i;
        if (atom < NN) {
#pragma unroll
            for (int c = 0; c < 4; c++)
                out[(size_t)atom * DD + jg + 32 * c] = sum2(acc[i][c]);
        }
    }
}

// ================= wmma edge kernel: 64 edges/block, 256 threads, 3 blocks/SM ========
// b-fragments load straight from pre-split global weights (L1-resident, shared
// across blocks). smem holds only the h tiles + f32 stages (stg2 overlays h).
#define HB_HI   0
#define HB_LO   9216
#define STG1    18432                 // f32 [64][68] = 17408 -> end 35840
#define STG2    0                     // f32 [64][132] = 33792, overlays h after GEMM2
#define WE_SMEM 35840
#define H_LD    72

__global__ __launch_bounds__(256, 3)
void edge_kernel(const float* __restrict__ A, float* __restrict__ sn,
                 const void* __restrict__ srcp, const void* __restrict__ dstp,
                 const __nv_bfloat16* __restrict__ whh, const __nv_bfloat16* __restrict__ whl,
                 const __nv_bfloat16* __restrict__ woh, const __nv_bfloat16* __restrict__ wol,
                 const float* __restrict__ bh_t, const float* __restrict__ bo_t,
                 const float* __restrict__ bi_t) {
    extern __shared__ char smc[];
    int tid = threadIdx.x;
    int w = tid >> 5, lane = tid & 31;
    int eb = blockIdx.x * 64;

    __nv_bfloat16* h_hi = (__nv_bfloat16*)(smc + HB_HI);
    __nv_bfloat16* h_lo = (__nv_bfloat16*)(smc + HB_LO);
    float* stg1 = (float*)(smc + STG1);
    float* stg2 = (float*)(smc + STG2);

    // ---- gather + layer0 -> h0 bf16 hi/lo ----
    {
        int e = tid >> 2;
        int j0 = (tid & 3) * 16;
        int d = load_idx(dstp, eb + e);
        int s = load_idx(srcp, eb + e);
        const float* ad = A + (size_t)d * DD + j0;
        const float* as = A + (size_t)s * DD + 64 + j0;
#pragma unroll
        for (int q = 0; q < 4; q++) {
            float4 x = *(const float4*)(ad + 4 * q);
            float4 y = *(const float4*)(as + 4 * q);
            float4 b = *(const float4*)(bi_t + j0 + 4 * q);
            float r0 = fmaxf(x.x + y.x + b.x, 0.f);
            float r1 = fmaxf(x.y + y.y + b.y, 0.f);
            float r2 = fmaxf(x.z + y.z + b.z, 0.f);
            float r3 = fmaxf(x.w + y.w + b.w, 0.f);
            uint32_t h0, l0, h1, l1;
            split2(r0, r1, h0, l0);
            split2(r2, r3, h1, l1);
            int boff = e * 144 + (j0 + 4 * q) * 2;
            *(uint2*)(smc + HB_HI + boff) = make_uint2(h0, h1);
            *(uint2*)(smc + HB_LO + boff) = make_uint2(l0, l1);
        }
    }
    __syncthreads();

    // ---- GEMM1: [64e x 64j x 64k], b-frags from global (ld 64) ----
    {
        int tm = w >> 1;
        int tn0 = (2 * w) & 3;
        wmma::fragment<wmma::accumulator, 16, 16, 16, float> acc[2];
        wmma::fill_fragment(acc[0], 0.f);
        wmma::fill_fragment(acc[1], 0.f);
#pragma unroll
        for (int kk = 0; kk < 4; kk++) {
            wmma::fragment<wmma::matrix_a, 16, 16, 16, __nv_bfloat16, wmma::row_major> a_hi, a_lo;
            wmma::load_matrix_sync(a_hi, h_hi + tm * 16 * H_LD + kk * 16, H_LD);
            wmma::load_matrix_sync(a_lo, h_lo + tm * 16 * H_LD + kk * 16, H_LD);
#pragma unroll
            for (int q = 0; q < 2; q++) {
                wmma::fragment<wmma::matrix_b, 16, 16, 16, __nv_bfloat16, wmma::row_major> b_hi, b_lo;
                wmma::load_matrix_sync(b_hi, whh + kk * 16 * 64 + (tn0 + q) * 16, 64);
                wmma::load_matrix_sync(b_lo, whl + kk * 16 * 64 + (tn0 + q) * 16, 64);
                wmma::mma_sync(acc[q], a_hi, b_hi, acc[q]);
                wmma::mma_sync(acc[q], a_hi, b_lo, acc[q]);
                wmma::mma_sync(acc[q], a_lo, b_hi, acc[q]);
            }
        }
        wmma::store_matrix_sync(stg1 + tm * 16 * 68 + tn0 * 16, acc[0], 68, wmma::mem_row_major);
        wmma::store_matrix_sync(stg1 + tm * 16 * 68 + (tn0 + 1) * 16, acc[1], 68, wmma::mem_row_major);
    }
    __syncthreads();   // stg1 visible; all h0 a-frag reads complete

    // ---- epilogue1: bias+relu, re-split -> h1 hi/lo (overwrites h0) ----
    {
        int e = tid >> 2;
        int j0 = (tid & 3) * 16;
#pragma unroll
        for (int q = 0; q < 4; q++) {
            int j = j0 + 4 * q;
            float4 v = *(const float4*)(stg1 + e * 68 + j);
            float4 b = *(const float4*)(bh_t + j);
            float r0 = fmaxf(v.x + b.x, 0.f);
            float r1 = fmaxf(v.y + b.y, 0.f);
            float r2 = fmaxf(v.z + b.z, 0.f);
            float r3 = fmaxf(v.w + b.w, 0.f);
            uint32_t h0, l0, h1, l1;
            split2(r0, r1, h0, l0);
            split2(r2, r3, h1, l1);
            int boff = e * 144 + j * 2;
            *(uint2*)(smc + HB_HI + boff) = make_uint2(h0, h1);
            *(uint2*)(smc + HB_LO + boff) = make_uint2(l0, l1);
        }
    }
    __syncthreads();

    // ---- GEMM2: [64e x 128j x 64k], b-frags from global (ld 128) ----
    {
        int tm = w >> 1;
        int tnb = (w & 1) * 4;
        wmma::fragment<wmma::accumulator, 16, 16, 16, float> acc[4];
#pragma unroll
        for (int q = 0; q < 4; q++) wmma::fill_fragment(acc[q], 0.f);
#pragma unroll
        for (int kk = 0; kk < 4; kk++) {
            wmma::fragment<wmma::matrix_a, 16, 16, 16, __nv_bfloat16, wmma::row_major> a_hi, a_lo;
            wmma::load_matrix_sync(a_hi, h_hi + tm * 16 * H_LD + kk * 16, H_LD);
            wmma::load_matrix_sync(a_lo, h_lo + tm * 16 * H_LD + kk * 16, H_LD);
#pragma unroll
            for (int q = 0; q < 4; q++) {
                wmma::fragment<wmma::matrix_b, 16, 16, 16, __nv_bfloat16, wmma::row_major> b_hi, b_lo;
                wmma::load_matrix_sync(b_hi, woh + kk * 16 * 128 + (tnb + q) * 16, 128);
                wmma::load_matrix_sync(b_lo, wol + kk * 16 * 128 + (tnb + q) * 16, 128);
                wmma::mma_sync(acc[q], a_hi, b_hi, acc[q]);
                wmma::mma_sync(acc[q], a_hi, b_lo, acc[q]);
                wmma::mma_sync(acc[q], a_lo, b_hi, acc[q]);
            }
        }
        __syncthreads();   // all h1 reads done before stg2 overlays h
#pragma unroll
        for (int q = 0; q < 4; q++)
            wmma::store_matrix_sync(stg2 + tm * 16 * 132 + (tnb + q) * 16, acc[q], 132,
                                    wmma::mem_row_major);
    }
    __syncthreads();

    // ---- epilogue2: bias+relu + coalesced atomic scatter ----
    {
        int e0 = (tid >> 5) * 8;
#pragma unroll
        for (int i = 0; i < 8; i++) {
            int e = e0 + i;
            int de = load_idx(dstp, eb + e);    // L1-hot
            float* row = sn + (size_t)de * DD;
#pragma unroll
            for (int c = 0; c < 4; c++) {
                int j = lane + 32 * c;
                float v = fmaxf(stg2[e * 132 + j] + __ldg(bo_t + j), 0.f);
                atomicAdd(row + j, v);          // REDG, coalesced over j
            }
        }
    }
}

// ---------------- molecule pooling ----------------
__global__ void pool_kernel(const float* __restrict__ s, const void* __restrict__ molp,
                            float* __restrict__ mol) {
    int i = blockIdx.x * blockDim.x + threadIdx.x;
    int stride = gridDim.x * blockDim.x;
    for (; i < NN * 32; i += stride) {
        int atom = i >> 5, q = (i & 31) * 4;
        int m = load_idx(molp, atom);
        float4 v = *(const float4*)&s[(size_t)atom * DD + q];
        float* row = &mol[m * DD + q];
        atomicAdd(row + 0, v.x);
        atomicAdd(row + 1, v.y);
        atomicAdd(row + 2, v.z);
        atomicAdd(row + 3, v.w);
    }
}

// ---------------- final MLP ----------------
__global__ void mlp_kernel(const float* __restrict__ mol,
                           const float* __restrict__ w1, const float* __restrict__ b1,
                           const float* __restrict__ w2, const float* __restrict__ b2,
                           const float* __restrict__ w3, const float* __restrict__ b3,
                           float* __restrict__ out) {
    __shared__ float mr[128], a1[64], a2[64];
    int m = blockIdx.x, tid = threadIdx.x;
    mr[tid]      = mol[m * DD + tid];
    mr[tid + 64] = mol[m * DD + tid + 64];
    __syncthreads();
    float acc = b1[tid];
    for (int k = 0; k < 128; k++) acc = fmaf(mr[k], w1[k * 64 + tid], acc);
    a1[tid] = fmaxf(acc, 0.f);
    __syncthreads();
    acc = b2[tid];
    for (int k = 0; k < 64; k++) acc = fmaf(a1[k], w2[k * 64 + tid], acc);
    a2[tid] = fmaxf(acc, 0.f);
    __syncthreads();
    if (tid < OUTC) {
        acc = b3[tid];
        for (int k = 0; k < 64; k++) acc = fmaf(a2[k], w3[k * OUTC + tid], acc);
        out[m * OUTC + tid] = acc;
    }
}

// ---------------- host launcher ----------------
extern "C" void kernel_launch(void* const* d_in, const int* in_sizes, int n_in,
                              void* d_out, int out_size) {
    (void)in_sizes; (void)n_in; (void)out_size;
    const float* states = (const float*)d_in[0];
    const float* Win    = (const float*)d_in[1];
    const float* b_in   = (const float*)d_in[2];
    const float* Wh     = (const float*)d_in[3];
    const float* b_h    = (const float*)d_in[4];
    const float* Wout   = (const float*)d_in[5];
    const float* b_out  = (const float*)d_in[6];
    const float* fc1_w  = (const float*)d_in[7];
    const float* fc1_b  = (const float*)d_in[8];
    const float* fc2_w  = (const float*)d_in[9];
    const float* fc2_b  = (const float*)d_in[10];
    const float* out_w  = (const float*)d_in[11];
    const float* out_b  = (const float*)d_in[12];
    const void*  src    = d_in[13];
    const void*  dst    = d_in[14];
    const void*  molid  = d_in[15];
    float* out = (float*)d_out;

    cudaFuncSetAttribute(precompute_kernel,
        cudaFuncAttributeMaxDynamicSharedMemorySize, PC_SMEM_BYTES);
    cudaFuncSetAttribute(edge_kernel,
        cudaFuncAttributeMaxDynamicSharedMemorySize, WE_SMEM);

    float *s1, *s2, *ab, *mol;
    __nv_bfloat16 *whh, *whl, *woh, *wol;
    cudaGetSymbolAddress((void**)&s1, g_s1);
    cudaGetSymbolAddress((void**)&s2, g_s2);
    cudaGetSymbolAddress((void**)&ab, g_Abuf);
    cudaGetSymbolAddress((void**)&mol, g_mol);
    cudaGetSymbolAddress((void**)&whh, g_whh);
    cudaGetSymbolAddress((void**)&whl, g_whl);
    cudaGetSymbolAddress((void**)&woh, g_woh);
    cudaGetSymbolAddress((void**)&wol, g_wol);

    detect_kernel<<<1, 32>>>((const int*)src);
    split_w_kernel<<<72, 256>>>(Wh, Wout);

    const int pc_grid = (NN + 63) / 64;   // 782
    const int e_grid  = EE / 64;          // 6250
    const int z_grid  = 296;

    const float* sin = states;
    float* bufs[2] = {s1, s2};
    for (int t = 0; t < 3; t++) {
        float* sout = bufs[t & 1];
        precompute_kernel<<<pc_grid, 256, PC_SMEM_BYTES>>>(sin, ab, Win + (size_t)t * 2 * DD * 64);
        zero_kernel<<<z_grid, 256>>>((float4*)sout, NN * DD / 4);
        edge_kernel<<<e_grid, 256, WE_SMEM>>>(
            ab, sout, src, dst,
            whh + (size_t)t * 64 * 64, whl + (size_t)t * 64 * 64,
            woh + (size_t)t * 64 * 128, wol + (size_t)t * 64 * 128,
            b_h + (size_t)t * 64, b_out + (size_t)t * DD,
            b_in + (size_t)t * 64);
        sin = sout;
    }

    zero_kernel<<<8, 256>>>((float4*)mol, NMOL * DD / 4);
    pool_kernel<<<592, 256>>>(sin, molid, mol);
    mlp_kernel<<<NMOL, 64>>>(mol, fc1_w, fc1_b, fc2_w, fc2_b, out_w, out_b, out);
}